// round 11
// baseline (speedup 1.0000x reference)
#include <cuda_runtime.h>
#include <cmath>

#define S_LEN  1024
#define BATCHN 128
#define IDIM   256
#define HDIM   512
#define ODIM   64

typedef unsigned long long ull;

// ---------- f32x2 packed helpers ----------
__device__ __forceinline__ ull splat2(float x) {
    ull r; asm("mov.b64 %0, {%1, %1};" : "=l"(r) : "f"(x)); return r;
}
__device__ __forceinline__ ull ffma2(ull a, ull b, ull c) {
    ull d; asm("fma.rn.f32x2 %0, %1, %2, %3;" : "=l"(d) : "l"(a), "l"(b), "l"(c)); return d;
}
__device__ __forceinline__ ull add2(ull a, ull b) {
    ull d; asm("add.rn.f32x2 %0, %1, %2;" : "=l"(d) : "l"(a), "l"(b)); return d;
}
__device__ __forceinline__ float2 upk2(ull v) {
    float2 f; asm("mov.b64 {%0, %1}, %2;" : "=f"(f.x), "=f"(f.y) : "l"(v)); return f;
}
__device__ __forceinline__ unsigned s2u32(const void* p) {
    unsigned a;
    asm("{ .reg .u64 t; cvta.to.shared.u64 t, %1; cvt.u32.u64 %0, t; }" : "=r"(a) : "l"(p));
    return a;
}
__device__ __forceinline__ unsigned mapa_rank(unsigned a, unsigned r) {
    unsigned d; asm("mapa.shared::cluster.u32 %0, %1, %2;" : "=r"(d) : "r"(a), "r"(r));
    return d;
}
__device__ __forceinline__ void bulk_s2c(unsigned dst, unsigned src, unsigned bytes,
                                         unsigned mbar) {
    asm volatile(
        "cp.async.bulk.shared::cluster.shared::cta.mbarrier::complete_tx::bytes "
        "[%0], [%1], %2, [%3];"
        :: "r"(dst), "r"(src), "r"(bytes), "r"(mbar) : "memory");
}
__device__ __forceinline__ void mbar_init(unsigned mbar, unsigned cnt) {
    asm volatile("mbarrier.init.shared.b64 [%0], %1;" :: "r"(mbar), "r"(cnt) : "memory");
}
__device__ __forceinline__ void mbar_expect_tx(unsigned mbar, unsigned bytes) {
    asm volatile("mbarrier.arrive.expect_tx.shared.b64 _, [%0], %1;"
                 :: "r"(mbar), "r"(bytes) : "memory");
}
__device__ __forceinline__ void mbar_wait_parity(unsigned mbar, unsigned parity) {
    asm volatile(
        "{\n\t"
        ".reg .pred P;\n"
        "LW_%=:\n\t"
        "mbarrier.try_wait.parity.acquire.cta.shared::cta.b64 P, [%0], %1, 0x989680;\n\t"
        "@P bra LD_%=;\n\t"
        "bra LW_%=;\n"
        "LD_%=:\n\t"
        "}"
        :: "r"(mbar), "r"(parity) : "memory");
}
__device__ __forceinline__ unsigned elect1() {
    unsigned p;
    asm volatile("{\n\t.reg .pred p;\n\telect.sync _|p, 0xFFFFFFFF;\n\t"
                 "selp.b32 %0, 1, 0, p;\n\t}" : "=r"(p));
    return p;
}
__device__ __forceinline__ void bar_sync_n(unsigned id, unsigned n) {
    asm volatile("bar.sync %0, %1;" :: "r"(id), "r"(n) : "memory");
}

// ---------- scratch (device globals: allocation-free rule) ----------
__device__ float g_xp[(size_t)BATCHN * S_LEN * HDIM];  // X@W_ih + b_hh, [b][s][h]
__device__ float g_h [(size_t)BATCHN * S_LEN * HDIM];  // hidden states,  [b][s][h]

// ============================================================================
// Kernel A: g_xp[M,512] = X[M,256] @ W_ih[256,512] + b_hh, M = 131072
// ============================================================================
__global__ void __launch_bounds__(256, 2) xproj_kernel(
    const float* __restrict__ X, const float* __restrict__ Wih,
    const float* __restrict__ bhh)
{
    __shared__ float As[128][17];
    __shared__ float Bs[16][128];
    const int tid = threadIdx.x;
    const int m0 = blockIdx.x * 128;
    const int n0 = blockIdx.y * 128;
    const int tx = tid & 15, ty = tid >> 4;

    ull acc[8][4];
#pragma unroll
    for (int i = 0; i < 8; i++)
#pragma unroll
        for (int j = 0; j < 4; j++) acc[i][j] = 0ull;

    for (int k0 = 0; k0 < IDIM; k0 += 16) {
#pragma unroll
        for (int i = 0; i < 2; i++) {
            int f4  = tid + i * 256;
            int row = f4 >> 2;
            int c4  = (f4 & 3) << 2;
            float4 v = *(const float4*)(X + (size_t)(m0 + row) * IDIM + k0 + c4);
            As[row][c4 + 0] = v.x; As[row][c4 + 1] = v.y;
            As[row][c4 + 2] = v.z; As[row][c4 + 3] = v.w;
        }
#pragma unroll
        for (int i = 0; i < 2; i++) {
            int f4  = tid + i * 256;
            int row = f4 >> 5;
            int c4  = (f4 & 31) << 2;
            *(float4*)&Bs[row][c4] =
                *(const float4*)(Wih + (size_t)(k0 + row) * HDIM + n0 + c4);
        }
        __syncthreads();
#pragma unroll
        for (int k = 0; k < 16; k++) {
            ulonglong2 bv0 = *(const ulonglong2*)&Bs[k][tx * 4];
            ulonglong2 bv1 = *(const ulonglong2*)&Bs[k][64 + tx * 4];
#pragma unroll
            for (int i = 0; i < 8; i++) {
                ull a2 = splat2(As[ty * 8 + i][k]);
                acc[i][0] = ffma2(a2, bv0.x, acc[i][0]);
                acc[i][1] = ffma2(a2, bv0.y, acc[i][1]);
                acc[i][2] = ffma2(a2, bv1.x, acc[i][2]);
                acc[i][3] = ffma2(a2, bv1.y, acc[i][3]);
            }
        }
        __syncthreads();
    }

#pragma unroll
    for (int i = 0; i < 8; i++) {
        float* dst = g_xp + (size_t)(m0 + ty * 8 + i) * HDIM + n0;
#pragma unroll
        for (int j = 0; j < 4; j++) {
            int n = (j < 2) ? (tx * 4 + j * 2) : (64 + tx * 4 + (j - 2) * 2);
            float2 v = upk2(acc[i][j]);
            v.x += bhh[n0 + n];
            v.y += bhh[n0 + n + 1];
            *(float2*)(dst + n) = v;
        }
    }
}

// empty launch to shift ncu's fixed profiled-launch slot onto rnn_kernel
__global__ void dummy_kernel() {}

// ============================================================================
// Kernel B: serial recurrence, PARTIAL-SUM exchange.
// 16 clusters x 8 CTAs, 512 threads. CTA r owns W k-rows [64r,64r+64) (all
// 512 cols, as ull col-pairs) and computes/keeps h for cols [64r,64r+64).
//
// Per step t:
//  - warp-pair p (warps 2p,2p+1) computes partial dots over local k-chunk for
//    dest CTA s=(rank+p)&7's 32 col-pairs x 8 batches -> stg[slot][p] (2KB),
//    pair-bar, leader bulk-copies it to s's inbox[slot][rank] with
//    complete_tx to s's mb[rank][slot] (expect 2048B). Pushes are staggered
//    through phase1.
//  - reducer warp w (0-7): waits mb[w][slot], re-arms, bar(256), reduces 8
//    slices (+xp), tanh, STG h to g_h, stores h SPLATTED into hsp[slot].
//  - bar(512); next phase1 reads hsp[slot].
// ============================================================================
#define NT 512
// ull offsets: Wp[64][256]=16384 | inbox[2][8][8][32]=4096 | stg same=4096 |
//              hsp[2][64][8]=1024 | 16 mbars
#define U_INB 16384
#define U_STG 20480
#define U_HSP 24576
#define U_MB  25600
#define SMEMB_BYTES (25600 * 8 + 128)
#define INB_B 131072u
#define STG_B 163840u
#define MB_B  204800u
#define BSTRIDE ((size_t)S_LEN * HDIM)
#define BLK_BYTES 2048u

__global__ void __launch_bounds__(NT, 1) __cluster_dims__(8, 1, 1)
rnn_kernel(const float* __restrict__ Whh)
{
    extern __shared__ float sm[];
    ull* Wp    = (ull*)sm;           // [k64][jp256] col-pairs, all 512 cols
    ull* inbox = Wp + U_INB;         // [slot2][src8][b8][jp32]
    ull* stg   = Wp + U_STG;         // [slot2][pair8][b8][jp32]
    ull* hsp   = Wp + U_HSP;         // [slot2][k64][b8] splatted h

    const int tid  = threadIdx.x;
    const int rank = blockIdx.x & 7;
    const int g    = blockIdx.x >> 3;
    const int c0   = rank * 64;
    const unsigned smb    = s2u32(sm);
    const unsigned mb_loc = smb + MB_B;      // mb[src][slot]: +(src*2+slot)*8

    if (tid == 0) {
#pragma unroll
        for (int i = 0; i < 16; i++) {
            mbar_init(mb_loc + i * 8, 1);
            mbar_expect_tx(mb_loc + i * 8, BLK_BYTES);
        }
    }

    // Load W k-rows [64*rank, +64), all 512 cols, as col-pairs (128KB)
    for (int i = tid; i < 64 * 256; i += NT) {
        int k = i >> 8, jp = i & 255;
        *(float2*)(Wp + i) =
            *(const float2*)(Whh + (size_t)(64 * rank + k) * HDIM + 2 * jp);
    }
    // zero hsp both slots (h0 = 0)
    for (int i = tid; i < 2 * 64 * 8; i += NT) hsp[i] = 0ull;
    __syncthreads();
    asm volatile("barrier.cluster.arrive.aligned;" ::: "memory");
    asm volatile("barrier.cluster.wait.aligned;"   ::: "memory");

    const int w  = tid >> 5, l = tid & 31;
    const int rg = l >> 4,  ls = l & 15;
    const int p  = w >> 1;                       // warp-pair index 0-7
    const int s  = (rank + p) & 7;               // destination CTA
    const int jpl = (w & 1) * 16 + ls;           // jp within dest's 32 pairs

    // phase-1 pointers
    const ull* wsp = Wp + 32 * s + jpl;          // + k*256
    const ull* hk0 = hsp + rg * 4;               // + slot*512 + k*8
    ull*       sg  = stg + p * 256 + rg * 128 + jpl;  // + slot*2048, [q*32]

    // reducer (warps 0-7): src = w for the wait; value (b=w, jp=l)
    const unsigned mb_w = mb_loc + (unsigned)(w * 16);   // + slot*8
    const ull* ib = inbox + w * 32 + l;          // + slot*2048, [src*256]
    const float* xpp = g_xp + ((size_t)(g * 8 + w)) * BSTRIDE + c0 + 2 * l;
    float*       ghw = g_h  + ((size_t)(g * 8 + w)) * BSTRIDE + c0 + 2 * l;
    ull*         hd  = hsp + (2 * l) * 8 + w;    // + slot*512, [+8] for k=2l+1

    // push targets (leader = even warp): dest s's inbox[slot][rank] + mb[rank][slot]
    const unsigned dst_hx = mapa_rank(smb + INB_B + (unsigned)rank * 2048u, (unsigned)s);
    const unsigned dst_mb = mapa_rank(mb_loc + (unsigned)(rank * 16), (unsigned)s);
    const unsigned src_st = smb + STG_B + (unsigned)p * 2048u;
    const bool     leader = ((w & 1) == 0);

    for (int t = 0; t < S_LEN; t++) {
        const int slot = t & 1;                  // write slot; h read = slot^1
        const int rbuf = slot ^ 1;

        // xp prefetch (reducers), consumed after phase 1 + wait
        ull xv = 0;
        if (w < 8) xv = *(const ull*)(xpp + (size_t)t * HDIM);

        // ---- phase 1: 1 col-pair x 8 batches per lane over 64 local k ----
        const ull* hk = hk0 + rbuf * 512;
        ull a0 = 0, a1 = 0, a2 = 0, a3 = 0;
#pragma unroll 8
        for (int k = 0; k < 64; k++) {
            ull wv = wsp[k * 256];
            ulonglong2 hA = *(const ulonglong2*)(hk + k * 8);
            ulonglong2 hB = *(const ulonglong2*)(hk + k * 8 + 2);
            a0 = ffma2(wv, hA.x, a0);
            a1 = ffma2(wv, hA.y, a1);
            a2 = ffma2(wv, hB.x, a2);
            a3 = ffma2(wv, hB.y, a3);
        }
        {
            ull* sq = sg + slot * 2048;
            sq[0]  = a0;
            sq[32] = a1;
            sq[64] = a2;
            sq[96] = a3;
        }
        bar_sync_n(1u + (unsigned)p, 64u);       // pair barrier: stg slice ready

        if (leader && elect1()) {
            asm volatile("fence.proxy.async.shared::cta;" ::: "memory");
            bulk_s2c(dst_hx + (unsigned)slot * 16384u,
                     src_st + (unsigned)slot * 16384u,
                     BLK_BYTES,
                     dst_mb + (unsigned)slot * 8u);
        }

        // ---- reducers: wait own source, fan-in, reduce, tanh, store ----
        if (w < 8) {
            const unsigned mb = mb_w + (unsigned)(slot * 8);
            mbar_wait_parity(mb, (unsigned)((t >> 1) & 1));
            if (elect1()) mbar_expect_tx(mb, BLK_BYTES);
            bar_sync_n(9u, 256u);                // all 8 sources in

            const ull* iq = ib + slot * 2048;
            ull q0 = add2(iq[0],        iq[256]);
            ull q1 = add2(iq[512],      iq[768]);
            ull q2 = add2(iq[1024],     iq[1280]);
            ull q3 = add2(iq[1536],     iq[1792]);
            q0 = add2(q0, q1);
            q2 = add2(q2, q3);
            ull sum = add2(xv, add2(q0, q2));
            float2 sv = upk2(sum);
            float h0 = tanhf(sv.x);
            float h1 = tanhf(sv.y);
            *(float2*)(ghw + (size_t)t * HDIM) = make_float2(h0, h1);
            ull* hq = hd + slot * 512;
            hq[0] = splat2(h0);                  // k = 2l
            hq[8] = splat2(h1);                  // k = 2l+1
        }
        bar_sync_n(10u, 512u);                   // h(t) splats visible to all
    }
}

// ============================================================================
// Kernel C: out[M,64] = g_h[M,512] @ W_ho[512,64] + b_ho, M = 131072
// ============================================================================
__global__ void __launch_bounds__(256) out_kernel(
    const float* __restrict__ Who, const float* __restrict__ bho,
    float* __restrict__ out)
{
    __shared__ float As[128][17];
    __shared__ float Bs[16][64];
    const int tid = threadIdx.x;
    const int m0 = blockIdx.x * 128;
    const int tx = tid & 15, ty = tid >> 4;

    ull acc[8][2];
#pragma unroll
    for (int i = 0; i < 8; i++) { acc[i][0] = 0ull; acc[i][1] = 0ull; }

    for (int k0 = 0; k0 < HDIM; k0 += 16) {
#pragma unroll
        for (int i = 0; i < 2; i++) {
            int f4  = tid + i * 256;
            int row = f4 >> 2;
            int c4  = (f4 & 3) << 2;
            float4 v = *(const float4*)(g_h + (size_t)(m0 + row) * HDIM + k0 + c4);
            As[row][c4 + 0] = v.x; As[row][c4 + 1] = v.y;
            As[row][c4 + 2] = v.z; As[row][c4 + 3] = v.w;
        }
        {
            int row = tid >> 4;
            int c4  = (tid & 15) << 2;
            *(float4*)&Bs[row][c4] =
                *(const float4*)(Who + (size_t)(k0 + row) * ODIM + c4);
        }
        __syncthreads();
#pragma unroll
        for (int k = 0; k < 16; k++) {
            ulonglong2 bv = *(const ulonglong2*)&Bs[k][tx * 4];
#pragma unroll
            for (int i = 0; i < 8; i++) {
                ull a2 = splat2(As[ty * 8 + i][k]);
                acc[i][0] = ffma2(a2, bv.x, acc[i][0]);
                acc[i][1] = ffma2(a2, bv.y, acc[i][1]);
            }
        }
        __syncthreads();
    }

    float bb0 = bho[tx * 4 + 0], bb1 = bho[tx * 4 + 1];
    float bb2 = bho[tx * 4 + 2], bb3 = bho[tx * 4 + 3];
#pragma unroll
    for (int i = 0; i < 8; i++) {
        float2 v0 = upk2(acc[i][0]); v0.x += bb0; v0.y += bb1;
        float2 v1 = upk2(acc[i][1]); v1.x += bb2; v1.y += bb3;
        float* dst = out + (size_t)(m0 + ty * 8 + i) * ODIM + tx * 4;
        *(float2*)(dst + 0) = v0;
        *(float2*)(dst + 2) = v1;
    }
}

// ============================================================================
extern "C" void kernel_launch(void* const* d_in, const int* in_sizes, int n_in,
                              void* d_out, int out_size)
{
    const float* X   = (const float*)d_in[0];   // [128,1024,256]
    const float* Whh = (const float*)d_in[1];   // [512,512]
    const float* Wih = (const float*)d_in[2];   // [256,512]
    const float* bhh = (const float*)d_in[3];   // [512]
    const float* Who = (const float*)d_in[4];   // [512,64]
    const float* bho = (const float*)d_in[5];   // [64]
    float* out = (float*)d_out;                 // [128,1024,64]

    cudaFuncSetAttribute(rnn_kernel,
                         cudaFuncAttributeMaxDynamicSharedMemorySize,
                         SMEMB_BYTES);

    xproj_kernel<<<dim3(1024, 4, 1), 256>>>(X, Wih, bhh);
    dummy_kernel<<<1, 32>>>();
    dummy_kernel<<<1, 32>>>();
    rnn_kernel<<<128, NT, SMEMB_BYTES>>>(Whh);
    out_kernel<<<1024, 256>>>(Who, bho, out);
}

// round 13
// speedup vs baseline: 2.1674x; 2.1674x over previous
#include <cuda_runtime.h>
#include <cmath>

#define S_LEN  1024
#define BATCHN 128
#define IDIM   256
#define HDIM   512
#define ODIM   64

typedef unsigned long long ull;

// ---------- f32x2 packed helpers ----------
__device__ __forceinline__ ull splat2(float x) {
    ull r; asm("mov.b64 %0, {%1, %1};" : "=l"(r) : "f"(x)); return r;
}
__device__ __forceinline__ ull ffma2(ull a, ull b, ull c) {
    ull d; asm("fma.rn.f32x2 %0, %1, %2, %3;" : "=l"(d) : "l"(a), "l"(b), "l"(c)); return d;
}
__device__ __forceinline__ ull add2(ull a, ull b) {
    ull d; asm("add.rn.f32x2 %0, %1, %2;" : "=l"(d) : "l"(a), "l"(b)); return d;
}
__device__ __forceinline__ float2 upk2(ull v) {
    float2 f; asm("mov.b64 {%0, %1}, %2;" : "=f"(f.x), "=f"(f.y) : "l"(v)); return f;
}
__device__ __forceinline__ unsigned s2u32(const void* p) {
    unsigned a;
    asm("{ .reg .u64 t; cvta.to.shared.u64 t, %1; cvt.u32.u64 %0, t; }" : "=r"(a) : "l"(p));
    return a;
}
__device__ __forceinline__ unsigned mapa_rank(unsigned a, unsigned r) {
    unsigned d; asm("mapa.shared::cluster.u32 %0, %1, %2;" : "=r"(d) : "r"(a), "r"(r));
    return d;
}
__device__ __forceinline__ void bulk_s2c(unsigned dst, unsigned src, unsigned bytes,
                                         unsigned mbar) {
    asm volatile(
        "cp.async.bulk.shared::cluster.shared::cta.mbarrier::complete_tx::bytes "
        "[%0], [%1], %2, [%3];"
        :: "r"(dst), "r"(src), "r"(bytes), "r"(mbar) : "memory");
}
__device__ __forceinline__ void mbar_init(unsigned mbar, unsigned cnt) {
    asm volatile("mbarrier.init.shared.b64 [%0], %1;" :: "r"(mbar), "r"(cnt) : "memory");
}
__device__ __forceinline__ void mbar_expect_tx(unsigned mbar, unsigned bytes) {
    asm volatile("mbarrier.arrive.expect_tx.shared.b64 _, [%0], %1;"
                 :: "r"(mbar), "r"(bytes) : "memory");
}
__device__ __forceinline__ void mbar_wait_parity(unsigned mbar, unsigned parity) {
    asm volatile(
        "{\n\t"
        ".reg .pred P;\n"
        "LW_%=:\n\t"
        "mbarrier.try_wait.parity.acquire.cta.shared::cta.b64 P, [%0], %1, 0x989680;\n\t"
        "@P bra LD_%=;\n\t"
        "bra LW_%=;\n"
        "LD_%=:\n\t"
        "}"
        :: "r"(mbar), "r"(parity) : "memory");
}
__device__ __forceinline__ unsigned elect1() {
    unsigned p;
    asm volatile("{\n\t.reg .pred p;\n\telect.sync _|p, 0xFFFFFFFF;\n\t"
                 "selp.b32 %0, 1, 0, p;\n\t}" : "=r"(p));
    return p;
}

// ---------- scratch (device globals: allocation-free rule) ----------
__device__ float g_xp[(size_t)BATCHN * S_LEN * HDIM];  // X@W_ih + b_hh, [b][s][h]
__device__ float g_h [(size_t)BATCHN * S_LEN * HDIM];  // hidden states,  [b][s][h]

// ============================================================================
// Kernel A: g_xp[M,512] = X[M,256] @ W_ih[256,512] + b_hh, M = 131072
// ============================================================================
__global__ void __launch_bounds__(256, 2) xproj_kernel(
    const float* __restrict__ X, const float* __restrict__ Wih,
    const float* __restrict__ bhh)
{
    __shared__ float As[128][17];
    __shared__ float Bs[16][128];
    const int tid = threadIdx.x;
    const int m0 = blockIdx.x * 128;
    const int n0 = blockIdx.y * 128;
    const int tx = tid & 15, ty = tid >> 4;

    ull acc[8][4];
#pragma unroll
    for (int i = 0; i < 8; i++)
#pragma unroll
        for (int j = 0; j < 4; j++) acc[i][j] = 0ull;

    for (int k0 = 0; k0 < IDIM; k0 += 16) {
#pragma unroll
        for (int i = 0; i < 2; i++) {
            int f4  = tid + i * 256;
            int row = f4 >> 2;
            int c4  = (f4 & 3) << 2;
            float4 v = *(const float4*)(X + (size_t)(m0 + row) * IDIM + k0 + c4);
            As[row][c4 + 0] = v.x; As[row][c4 + 1] = v.y;
            As[row][c4 + 2] = v.z; As[row][c4 + 3] = v.w;
        }
#pragma unroll
        for (int i = 0; i < 2; i++) {
            int f4  = tid + i * 256;
            int row = f4 >> 5;
            int c4  = (f4 & 31) << 2;
            *(float4*)&Bs[row][c4] =
                *(const float4*)(Wih + (size_t)(k0 + row) * HDIM + n0 + c4);
        }
        __syncthreads();
#pragma unroll
        for (int k = 0; k < 16; k++) {
            ulonglong2 bv0 = *(const ulonglong2*)&Bs[k][tx * 4];
            ulonglong2 bv1 = *(const ulonglong2*)&Bs[k][64 + tx * 4];
#pragma unroll
            for (int i = 0; i < 8; i++) {
                ull a2 = splat2(As[ty * 8 + i][k]);
                acc[i][0] = ffma2(a2, bv0.x, acc[i][0]);
                acc[i][1] = ffma2(a2, bv0.y, acc[i][1]);
                acc[i][2] = ffma2(a2, bv1.x, acc[i][2]);
                acc[i][3] = ffma2(a2, bv1.y, acc[i][3]);
            }
        }
        __syncthreads();
    }

#pragma unroll
    for (int i = 0; i < 8; i++) {
        float* dst = g_xp + (size_t)(m0 + ty * 8 + i) * HDIM + n0;
#pragma unroll
        for (int j = 0; j < 4; j++) {
            int n = (j < 2) ? (tx * 4 + j * 2) : (64 + tx * 4 + (j - 2) * 2);
            float2 v = upk2(acc[i][j]);
            v.x += bhh[n0 + n];
            v.y += bhh[n0 + n + 1];
            *(float2*)(dst + n) = v;
        }
    }
}

// empty launch to shift ncu's fixed profiled-launch slot onto rnn_kernel
__global__ void dummy_kernel() {}

// ============================================================================
// Kernel B: serial recurrence (R9 structure + PRE-SPLATTED exchange).
// 16 clusters x 8 CTAs; rank r owns W_hh cols [64r,64r+64) as ull col-pairs.
// 512 threads (16 warps, 4/SMSP).
//
// hx block per source (4KB, ull): [grp2][kLocal64][bi4] of SPLATTED h pairs
// (h,h). Phase-1 per k-iter: 2 LDS.64 (W) + 2 LDS.128 (4 splatted h) +
// 8 FFMA2 — no MOV expansion.
// Per-source mbars mb[src][slot] (16), expect_tx = 4096 B each. Warp pair
// (2s,2s+1) waits only source s; self-source warps skip the wait (own block
// written by consumers via STS, ordered by sync #2).
// ============================================================================
#define NT 512
// ull offsets: Wp[512][32]=16384 | prt[16][8][32]=4096 | hx[2][8][512]=8192
#define U_PRT 16384
#define U_HX  20480                   // = U_PRT + 4096 (prt is 4096 ULLs!)
#define HX_BYTE 163840u               // U_HX * 8
#define MB_BYTE 229376u               // (U_HX + 8192) * 8
#define SMEMB_BYTES (229376 + 128)
#define BSTRIDE ((size_t)S_LEN * HDIM)
#define BLK_BYTES 4096u               // one splatted source block
#define SLOT_BYTES 32768u             // 8 blocks

__global__ void __launch_bounds__(NT, 1) __cluster_dims__(8, 1, 1)
rnn_kernel(const float* __restrict__ Whh)
{
    extern __shared__ float sm[];
    ull* Wp  = (ull*)sm;               // [k][jp], k stride 32 ull
    ull* prt = Wp + U_PRT;             // [w16][b8][jp32] = 4096 ull
    ull* hx  = Wp + U_HX;              // [slot2][src8][grp2][kLocal64][bi4]

    const int tid  = threadIdx.x;
    const int rank = blockIdx.x & 7;
    const int g    = blockIdx.x >> 3;
    const int c0   = rank * 64;
    const unsigned smb    = s2u32(sm);
    const unsigned mb_loc = smb + MB_BYTE;   // mb[src][slot]: +(src*2+slot)*8

    if (tid == 0) {
#pragma unroll
        for (int i = 0; i < 16; i++) {
            mbar_init(mb_loc + i * 8, 1);
            mbar_expect_tx(mb_loc + i * 8, BLK_BYTES);
        }
    }

    // Load W_hh slice once as column pairs (128KB)
    for (int i = tid; i < HDIM * 32; i += NT) {
        int k = i >> 5, jp = i & 31;
        *(float2*)(Wp + i) = *(const float2*)(Whh + (size_t)k * HDIM + c0 + 2 * jp);
    }
    // zero hx (h0 = 0), both slots
    for (int i = tid; i < 2 * 8 * 512; i += NT) hx[i] = 0ull;
    __syncthreads();
    asm volatile("barrier.cluster.arrive.aligned;" ::: "memory");
    asm volatile("barrier.cluster.wait.aligned;"   ::: "memory");

    const int w  = tid >> 5, l = tid & 31;
    const int rg = l >> 4,  ls = l & 15;
    const int kbeg = w * 32;
    const int sw   = w >> 1;            // source rank feeding this warp's k-chunk

    // phase-1 pointers
    const ull* wsp = Wp + (size_t)kbeg * 32 + ls;   // wsp[k*32], wsp[k*32+16]
    const ull* hxb = hx + sw * 512 + rg * 256 + (w & 1) * 128;  // + slot*4096 + k*4
    ull*       pw  = prt + w * 256 + (rg * 4) * 32; // + q*32 + ls (+16)

    // phase-2 mapping (warps 0-7): b = w, lane l = col-pair jp
    const ull* pr = prt + w * 32 + l;
    const float* xpp = g_xp + ((size_t)(g * 8 + w)) * BSTRIDE + c0 + 2 * l;
    float*       ghw = g_h  + ((size_t)(g * 8 + w)) * BSTRIDE + c0 + 2 * l;
    // own-block splatted STS target: hx[slot][rank][w>>2][2l(+1)][w&3]
    ull* hxo = hx + rank * 512 + (w >> 2) * 256 + 8 * l + (w & 3);  // + slot*4096

    // bulk targets: peer r's hx[0][rank] block + peer r's mb[rank][0]
    unsigned peer_hx[8], peer_mb[8];
    {
        const unsigned hx0 = smb + HX_BYTE + (unsigned)rank * BLK_BYTES;
        const unsigned mb0 = mb_loc + (unsigned)(rank * 16);
#pragma unroll
        for (int r = 0; r < 8; r++) {
            peer_hx[r] = mapa_rank(hx0, (unsigned)r);
            peer_mb[r] = mapa_rank(mb0, (unsigned)r);
        }
    }
    const unsigned src_loc = smb + HX_BYTE + (unsigned)rank * BLK_BYTES;
    const unsigned mb_src  = mb_loc + (unsigned)(sw * 16);
    const bool self_src    = (sw == rank);
    const bool rearm_warp  = ((w & 1) == 0);

    for (int t = 0; t < S_LEN; t++) {
        const int wb = t & 1, rb = wb ^ 1;

        // xp prefetch (warps 0-7), issued before the wait so it rides it
        ull xv = 0;
        if (w < 8) xv = *(const ull*)(xpp + (size_t)t * HDIM);

        // ---- per-source wait: only this warp's source block ----
        if (t > 0 && !self_src) {
            const unsigned mb = mb_src + (unsigned)(rb * 8);
            mbar_wait_parity(mb, (unsigned)(((t - 1) >> 1) & 1));
            if (rearm_warp && elect1()) mbar_expect_tx(mb, BLK_BYTES);
        }

        // ---- phase 1: 2 col-pairs x 4 batches per lane, 32 k, no MOVs ----
        const ull* hk = hxb + rb * 4096;
        ull a00 = 0, a01 = 0, a02 = 0, a03 = 0;
        ull a10 = 0, a11 = 0, a12 = 0, a13 = 0;
#pragma unroll 4
        for (int k = 0; k < 32; k++) {
            ull w0 = wsp[k * 32];
            ull w1 = wsp[k * 32 + 16];
            ulonglong2 hA = *(const ulonglong2*)(hk + k * 4);      // b rg*4+0,1
            ulonglong2 hB = *(const ulonglong2*)(hk + k * 4 + 2);  // b rg*4+2,3
            a00 = ffma2(w0, hA.x, a00);
            a01 = ffma2(w0, hA.y, a01);
            a02 = ffma2(w0, hB.x, a02);
            a03 = ffma2(w0, hB.y, a03);
            a10 = ffma2(w1, hA.x, a10);
            a11 = ffma2(w1, hA.y, a11);
            a12 = ffma2(w1, hB.x, a12);
            a13 = ffma2(w1, hB.y, a13);
        }
        pw[0 * 32 + ls]      = a00;
        pw[1 * 32 + ls]      = a01;
        pw[2 * 32 + ls]      = a02;
        pw[3 * 32 + ls]      = a03;
        pw[0 * 32 + ls + 16] = a10;
        pw[1 * 32 + ls + 16] = a11;
        pw[2 * 32 + ls + 16] = a12;
        pw[3 * 32 + ls + 16] = a13;
        __syncthreads();

        // ---- phase 2 (warps 0-7): tree-reduce 16 partials + xp, tanh ----
        if (w < 8) {
            ull q0 = add2(pr[0 * 256],  pr[1 * 256]);
            ull q1 = add2(pr[2 * 256],  pr[3 * 256]);
            ull q2 = add2(pr[4 * 256],  pr[5 * 256]);
            ull q3 = add2(pr[6 * 256],  pr[7 * 256]);
            ull q4 = add2(pr[8 * 256],  pr[9 * 256]);
            ull q5 = add2(pr[10 * 256], pr[11 * 256]);
            ull q6 = add2(pr[12 * 256], pr[13 * 256]);
            ull q7 = add2(pr[14 * 256], pr[15 * 256]);
            q0 = add2(q0, q1); q2 = add2(q2, q3);
            q4 = add2(q4, q5); q6 = add2(q6, q7);
            q0 = add2(q0, q2); q4 = add2(q4, q6);
            ull s = add2(xv, add2(q0, q4));
            float2 sv = upk2(s);
            float h0 = tanhf(sv.x);
            float h1 = tanhf(sv.y);
            *(float2*)(ghw + (size_t)t * HDIM) = make_float2(h0, h1);
            if (t < S_LEN - 1) {
                ull* hq = hxo + wb * 4096;
                hq[0] = splat2(h0);   // kLocal = 2l
                hq[4] = splat2(h1);   // kLocal = 2l+1
            }
        }
        if (t == S_LEN - 1) break;   // nobody needs h(S)

        __syncthreads();   // own-block STS visible + prt reads done

        if (tid < 8 && tid != rank) {
            asm volatile("fence.proxy.async.shared::cta;" ::: "memory");
            bulk_s2c(peer_hx[tid] + (unsigned)wb * SLOT_BYTES,
                     src_loc + (unsigned)wb * SLOT_BYTES,
                     BLK_BYTES,
                     peer_mb[tid] + (unsigned)wb * 8);
        }
    }
}

// ============================================================================
// Kernel C: out[M,64] = g_h[M,512] @ W_ho[512,64] + b_ho, M = 131072
// ============================================================================
__global__ void __launch_bounds__(256) out_kernel(
    const float* __restrict__ Who, const float* __restrict__ bho,
    float* __restrict__ out)
{
    __shared__ float As[128][17];
    __shared__ float Bs[16][64];
    const int tid = threadIdx.x;
    const int m0 = blockIdx.x * 128;
    const int tx = tid & 15, ty = tid >> 4;

    ull acc[8][2];
#pragma unroll
    for (int i = 0; i < 8; i++) { acc[i][0] = 0ull; acc[i][1] = 0ull; }

    for (int k0 = 0; k0 < HDIM; k0 += 16) {
#pragma unroll
        for (int i = 0; i < 2; i++) {
            int f4  = tid + i * 256;
            int row = f4 >> 2;
            int c4  = (f4 & 3) << 2;
            float4 v = *(const float4*)(g_h + (size_t)(m0 + row) * HDIM + k0 + c4);
            As[row][c4 + 0] = v.x; As[row][c4 + 1] = v.y;
            As[row][c4 + 2] = v.z; As[row][c4 + 3] = v.w;
        }
        {
            int row = tid >> 4;
            int c4  = (tid & 15) << 2;
            *(float4*)&Bs[row][c4] =
                *(const float4*)(Who + (size_t)(k0 + row) * ODIM + c4);
        }
        __syncthreads();
#pragma unroll
        for (int k = 0; k < 16; k++) {
            ulonglong2 bv = *(const ulonglong2*)&Bs[k][tx * 4];
#pragma unroll
            for (int i = 0; i < 8; i++) {
                ull a2 = splat2(As[ty * 8 + i][k]);
                acc[i][0] = ffma2(a2, bv.x, acc[i][0]);
                acc[i][1] = ffma2(a2, bv.y, acc[i][1]);
            }
        }
        __syncthreads();
    }

    float bb0 = bho[tx * 4 + 0], bb1 = bho[tx * 4 + 1];
    float bb2 = bho[tx * 4 + 2], bb3 = bho[tx * 4 + 3];
#pragma unroll
    for (int i = 0; i < 8; i++) {
        float2 v0 = upk2(acc[i][0]); v0.x += bb0; v0.y += bb1;
        float2 v1 = upk2(acc[i][1]); v1.x += bb2; v1.y += bb3;
        float* dst = out + (size_t)(m0 + ty * 8 + i) * ODIM + tx * 4;
        *(float2*)(dst + 0) = v0;
        *(float2*)(dst + 2) = v1;
    }
}

// ============================================================================
extern "C" void kernel_launch(void* const* d_in, const int* in_sizes, int n_in,
                              void* d_out, int out_size)
{
    const float* X   = (const float*)d_in[0];   // [128,1024,256]
    const float* Whh = (const float*)d_in[1];   // [512,512]
    const float* Wih = (const float*)d_in[2];   // [256,512]
    const float* bhh = (const float*)d_in[3];   // [512]
    const float* Who = (const float*)d_in[4];   // [512,64]
    const float* bho = (const float*)d_in[5];   // [64]
    float* out = (float*)d_out;                 // [128,1024,64]

    cudaFuncSetAttribute(rnn_kernel,
                         cudaFuncAttributeMaxDynamicSharedMemorySize,
                         SMEMB_BYTES);

    xproj_kernel<<<dim3(1024, 4, 1), 256>>>(X, Wih, bhh);
    dummy_kernel<<<1, 32>>>();
    dummy_kernel<<<1, 32>>>();
    rnn_kernel<<<128, NT, SMEMB_BYTES>>>(Whh);
    out_kernel<<<1024, 256>>>(Who, bho, out);
}

// round 14
// speedup vs baseline: 2.6608x; 1.2276x over previous
#include <cuda_runtime.h>
#include <cmath>

#define S_LEN  1024
#define BATCHN 128
#define IDIM   256
#define HDIM   512
#define ODIM   64

typedef unsigned long long ull;

// ---------- f32x2 packed helpers ----------
__device__ __forceinline__ ull splat2(float x) {
    ull r; asm("mov.b64 %0, {%1, %1};" : "=l"(r) : "f"(x)); return r;
}
__device__ __forceinline__ ull ffma2(ull a, ull b, ull c) {
    ull d; asm("fma.rn.f32x2 %0, %1, %2, %3;" : "=l"(d) : "l"(a), "l"(b), "l"(c)); return d;
}
__device__ __forceinline__ ull add2(ull a, ull b) {
    ull d; asm("add.rn.f32x2 %0, %1, %2;" : "=l"(d) : "l"(a), "l"(b)); return d;
}
__device__ __forceinline__ float2 upk2(ull v) {
    float2 f; asm("mov.b64 {%0, %1}, %2;" : "=f"(f.x), "=f"(f.y) : "l"(v)); return f;
}
__device__ __forceinline__ unsigned s2u32(const void* p) {
    unsigned a;
    asm("{ .reg .u64 t; cvta.to.shared.u64 t, %1; cvt.u32.u64 %0, t; }" : "=r"(a) : "l"(p));
    return a;
}
__device__ __forceinline__ unsigned mapa_rank(unsigned a, unsigned r) {
    unsigned d; asm("mapa.shared::cluster.u32 %0, %1, %2;" : "=r"(d) : "r"(a), "r"(r));
    return d;
}
__device__ __forceinline__ void bulk_s2c(unsigned dst, unsigned src, unsigned bytes,
                                         unsigned mbar) {
    asm volatile(
        "cp.async.bulk.shared::cluster.shared::cta.mbarrier::complete_tx::bytes "
        "[%0], [%1], %2, [%3];"
        :: "r"(dst), "r"(src), "r"(bytes), "r"(mbar) : "memory");
}
__device__ __forceinline__ void mbar_init(unsigned mbar, unsigned cnt) {
    asm volatile("mbarrier.init.shared.b64 [%0], %1;" :: "r"(mbar), "r"(cnt) : "memory");
}
__device__ __forceinline__ void mbar_expect_tx(unsigned mbar, unsigned bytes) {
    asm volatile("mbarrier.arrive.expect_tx.shared.b64 _, [%0], %1;"
                 :: "r"(mbar), "r"(bytes) : "memory");
}
__device__ __forceinline__ void mbar_wait_parity(unsigned mbar, unsigned parity) {
    asm volatile(
        "{\n\t"
        ".reg .pred P;\n"
        "LW_%=:\n\t"
        "mbarrier.try_wait.parity.acquire.cta.shared::cta.b64 P, [%0], %1, 0x989680;\n\t"
        "@P bra LD_%=;\n\t"
        "bra LW_%=;\n"
        "LD_%=:\n\t"
        "}"
        :: "r"(mbar), "r"(parity) : "memory");
}
__device__ __forceinline__ unsigned elect1() {
    unsigned p;
    asm volatile("{\n\t.reg .pred p;\n\telect.sync _|p, 0xFFFFFFFF;\n\t"
                 "selp.b32 %0, 1, 0, p;\n\t}" : "=r"(p));
    return p;
}
__device__ __forceinline__ void bar_sync_n(unsigned id, unsigned n) {
    asm volatile("bar.sync %0, %1;" :: "r"(id), "r"(n) : "memory");
}
__device__ __forceinline__ void bar_arrive_n(unsigned id, unsigned n) {
    asm volatile("bar.arrive %0, %1;" :: "r"(id), "r"(n) : "memory");
}

// ---------- scratch (device globals: allocation-free rule) ----------
__device__ float g_xp[(size_t)BATCHN * S_LEN * HDIM];  // X@W_ih + b_hh, [b][s][h]
__device__ float g_h [(size_t)BATCHN * S_LEN * HDIM];  // hidden states,  [b][s][h]

// ============================================================================
// Kernel A: g_xp[M,512] = X[M,256] @ W_ih[256,512] + b_hh, M = 131072
// ============================================================================
__global__ void __launch_bounds__(256, 2) xproj_kernel(
    const float* __restrict__ X, const float* __restrict__ Wih,
    const float* __restrict__ bhh)
{
    __shared__ float As[128][17];
    __shared__ float Bs[16][128];
    const int tid = threadIdx.x;
    const int m0 = blockIdx.x * 128;
    const int n0 = blockIdx.y * 128;
    const int tx = tid & 15, ty = tid >> 4;

    ull acc[8][4];
#pragma unroll
    for (int i = 0; i < 8; i++)
#pragma unroll
        for (int j = 0; j < 4; j++) acc[i][j] = 0ull;

    for (int k0 = 0; k0 < IDIM; k0 += 16) {
#pragma unroll
        for (int i = 0; i < 2; i++) {
            int f4  = tid + i * 256;
            int row = f4 >> 2;
            int c4  = (f4 & 3) << 2;
            float4 v = *(const float4*)(X + (size_t)(m0 + row) * IDIM + k0 + c4);
            As[row][c4 + 0] = v.x; As[row][c4 + 1] = v.y;
            As[row][c4 + 2] = v.z; As[row][c4 + 3] = v.w;
        }
#pragma unroll
        for (int i = 0; i < 2; i++) {
            int f4  = tid + i * 256;
            int row = f4 >> 5;
            int c4  = (f4 & 31) << 2;
            *(float4*)&Bs[row][c4] =
                *(const float4*)(Wih + (size_t)(k0 + row) * HDIM + n0 + c4);
        }
        __syncthreads();
#pragma unroll
        for (int k = 0; k < 16; k++) {
            ulonglong2 bv0 = *(const ulonglong2*)&Bs[k][tx * 4];
            ulonglong2 bv1 = *(const ulonglong2*)&Bs[k][64 + tx * 4];
#pragma unroll
            for (int i = 0; i < 8; i++) {
                ull a2 = splat2(As[ty * 8 + i][k]);
                acc[i][0] = ffma2(a2, bv0.x, acc[i][0]);
                acc[i][1] = ffma2(a2, bv0.y, acc[i][1]);
                acc[i][2] = ffma2(a2, bv1.x, acc[i][2]);
                acc[i][3] = ffma2(a2, bv1.y, acc[i][3]);
            }
        }
        __syncthreads();
    }

#pragma unroll
    for (int i = 0; i < 8; i++) {
        float* dst = g_xp + (size_t)(m0 + ty * 8 + i) * HDIM + n0;
#pragma unroll
        for (int j = 0; j < 4; j++) {
            int n = (j < 2) ? (tx * 4 + j * 2) : (64 + tx * 4 + (j - 2) * 2);
            float2 v = upk2(acc[i][j]);
            v.x += bhh[n0 + n];
            v.y += bhh[n0 + n + 1];
            *(float2*)(dst + n) = v;
        }
    }
}

// empty launch to shift ncu's fixed profiled-launch slot onto rnn_kernel
__global__ void dummy_kernel() {}

// ============================================================================
// Kernel B: serial recurrence (R9 + rotated push + decoupled producers).
// 16 clusters x 8 CTAs; rank r owns W_hh cols [64r,64r+64) as ull col-pairs.
// 512 threads. Warps 0-7 = consumers (phase1 + reduce + push), 8-15 =
// producers (phase1 only, bar.arrive, run max 1 step ahead; prt double-buf).
// Self-source producer warps (rank>=4) join the consumers' pre-push barrier
// (id 3, count 320) for own-block STS ordering; others wait per-source mbars.
// Push order rotated: dst = (rank+1+i)&7 — arrival stagger evened out.
// ============================================================================
#define NT 512
// float offsets: Wp 32768 | prt[2] 16384 | hx 8192 | mbars
#define F_PRT 32768
#define F_HX  49152
#define HX_BYTE 196608u
#define MB_BYTE 229376u
#define SMEMB_BYTES (229376 + 128)
#define BSTRIDE ((size_t)S_LEN * HDIM)
#define BLK_BYTES 2048u

__global__ void __launch_bounds__(NT, 1) __cluster_dims__(8, 1, 1)
rnn_kernel(const float* __restrict__ Whh)
{
    extern __shared__ float sm[];
    ull* Wp  = (ull*)sm;               // [k][jp], k stride 32 ull
    ull* prt = (ull*)(sm + F_PRT);     // [buf2][w16][b8][jp32]
    float* hx = sm + F_HX;             // [slot2][src8][grp2][kLocal64][bi4]

    const int tid  = threadIdx.x;
    const int rank = blockIdx.x & 7;
    const int g    = blockIdx.x >> 3;
    const int c0   = rank * 64;
    const unsigned smb    = s2u32(sm);
    const unsigned mb_loc = smb + MB_BYTE;   // mb[src][slot]: +(src*2+slot)*8

    if (tid == 0) {
#pragma unroll
        for (int i = 0; i < 16; i++) {
            mbar_init(mb_loc + i * 8, 1);
            mbar_expect_tx(mb_loc + i * 8, BLK_BYTES);
        }
    }

    // Load W_hh slice once as column pairs (128KB)
    for (int i = tid; i < HDIM * 32; i += NT) {
        int k = i >> 5, jp = i & 31;
        *(float2*)(Wp + i) = *(const float2*)(Whh + (size_t)k * HDIM + c0 + 2 * jp);
    }
    // zero hx (h0 = 0), both slots
    for (int i = tid; i < 2 * 8 * 512; i += NT) hx[i] = 0.f;
    __syncthreads();
    asm volatile("barrier.cluster.arrive.aligned;" ::: "memory");
    asm volatile("barrier.cluster.wait.aligned;"   ::: "memory");

    const int w  = tid >> 5, l = tid & 31;
    const int rg = l >> 4,  ls = l & 15;
    const int kbeg = w * 32;
    const int sw   = w >> 1;            // source rank feeding this warp's k-chunk
    const bool consumer  = (w < 8);
    const bool self_src  = (sw == rank);
    const unsigned b3n   = (rank >= 4) ? 320u : 256u;   // consumers (+ self producers)

    // phase-1 pointers
    const ull*   wsp = Wp + (size_t)kbeg * 32 + ls;   // wsp[k*32], wsp[k*32+16]
    const float* hxb = hx + sw * 512 + rg * 256 + (w & 1) * 128;  // + slot*4096

    // phase-2 mapping (warps 0-7): b = w, lane l = col-pair jp
    const float* xpp = g_xp + ((size_t)(g * 8 + w)) * BSTRIDE + c0 + 2 * l;
    float*       ghw = g_h  + ((size_t)(g * 8 + w)) * BSTRIDE + c0 + 2 * l;
    // own-block STS target: hx[slot][rank][w>>2][2l(+1)][w&3]
    float* hxo = hx + rank * 512 + (w >> 2) * 256 + 8 * l + (w & 3);  // + slot*4096

    // rotated bulk targets (i = 0..6): dst = (rank+1+i)&7
    unsigned peer_hx[7], peer_mb[7];
    {
        const unsigned hx0 = smb + HX_BYTE + (unsigned)rank * BLK_BYTES;
        const unsigned mb0 = mb_loc + (unsigned)(rank * 16);
#pragma unroll
        for (int i = 0; i < 7; i++) {
            unsigned r = (unsigned)((rank + 1 + i) & 7);
            peer_hx[i] = mapa_rank(hx0, r);
            peer_mb[i] = mapa_rank(mb0, r);
        }
    }
    const unsigned src_loc = smb + HX_BYTE + (unsigned)rank * BLK_BYTES;
    const unsigned mb_src  = mb_loc + (unsigned)(sw * 16);
    const bool rearm_warp  = ((w & 1) == 0);

    for (int t = 0; t < S_LEN; t++) {
        const int wb = t & 1, rb = wb ^ 1;

        // xp prefetch (consumers), issued before the wait so it rides it
        ull xv = 0;
        if (consumer) xv = *(const ull*)(xpp + (size_t)t * HDIM);

        // ---- per-source wait: only this warp's source block ----
        if (t > 0 && !self_src) {
            const unsigned mb = mb_src + (unsigned)(rb * 8);
            mbar_wait_parity(mb, (unsigned)(((t - 1) >> 1) & 1));
            if (rearm_warp && elect1()) mbar_expect_tx(mb, BLK_BYTES);
        }

        // ---- phase 1: 2 col-pairs x 4 batches per lane, 32 k ----
        const float* hk = hxb + rb * 4096;
        ull a00 = 0, a01 = 0, a02 = 0, a03 = 0;
        ull a10 = 0, a11 = 0, a12 = 0, a13 = 0;
#pragma unroll 4
        for (int k = 0; k < 32; k++) {
            ull w0 = wsp[k * 32];
            ull w1 = wsp[k * 32 + 16];
            float4 hv = *(const float4*)(hk + k * 4);
            ull h0 = splat2(hv.x), h1 = splat2(hv.y);
            ull h2 = splat2(hv.z), h3 = splat2(hv.w);
            a00 = ffma2(w0, h0, a00);
            a01 = ffma2(w0, h1, a01);
            a02 = ffma2(w0, h2, a02);
            a03 = ffma2(w0, h3, a03);
            a10 = ffma2(w1, h0, a10);
            a11 = ffma2(w1, h1, a11);
            a12 = ffma2(w1, h2, a12);
            a13 = ffma2(w1, h3, a13);
        }
        {
            ull* pw = prt + wb * 4096 + w * 256 + (rg * 4) * 32;
            pw[0 * 32 + ls]      = a00;
            pw[1 * 32 + ls]      = a01;
            pw[2 * 32 + ls]      = a02;
            pw[3 * 32 + ls]      = a03;
            pw[0 * 32 + ls + 16] = a10;
            pw[1 * 32 + ls + 16] = a11;
            pw[2 * 32 + ls + 16] = a12;
            pw[3 * 32 + ls + 16] = a13;
        }

        if (!consumer) {
            bar_arrive_n(1u, 512u);                 // partials(t) posted; run ahead
            if (self_src && t < S_LEN - 1)
                bar_sync_n(3u, b3n);                // order own-block STS(t) reads
            continue;
        }
        bar_sync_n(1u, 512u);                       // all 16 partials(t) in

        // ---- phase 2 (consumers): tree-reduce + xp, tanh ----
        const ull* pq = prt + wb * 4096 + w * 32 + l;
        ull q0 = add2(pq[0 * 256],  pq[1 * 256]);
        ull q1 = add2(pq[2 * 256],  pq[3 * 256]);
        ull q2 = add2(pq[4 * 256],  pq[5 * 256]);
        ull q3 = add2(pq[6 * 256],  pq[7 * 256]);
        ull q4 = add2(pq[8 * 256],  pq[9 * 256]);
        ull q5 = add2(pq[10 * 256], pq[11 * 256]);
        ull q6 = add2(pq[12 * 256], pq[13 * 256]);
        ull q7 = add2(pq[14 * 256], pq[15 * 256]);
        q0 = add2(q0, q1); q2 = add2(q2, q3);
        q4 = add2(q4, q5); q6 = add2(q6, q7);
        q0 = add2(q0, q2); q4 = add2(q4, q6);
        ull s = add2(xv, add2(q0, q4));
        float2 sv = upk2(s);
        float h0 = tanhf(sv.x);
        float h1 = tanhf(sv.y);

        if (t == S_LEN - 1) {
            *(float2*)(ghw + (size_t)t * HDIM) = make_float2(h0, h1);
            break;                                   // nobody needs h(S)
        }

        hxo[wb * 4096]     = h0;                     // own block, kLocal = 2l
        hxo[wb * 4096 + 4] = h1;                     // kLocal = 2l+1
        bar_sync_n(3u, b3n);                         // STS visible to pusher

        if (tid < 7) {
            asm volatile("fence.proxy.async.shared::cta;" ::: "memory");
            bulk_s2c(peer_hx[tid] + (unsigned)wb * 16384u,
                     src_loc + (unsigned)wb * 16384u,
                     BLK_BYTES,
                     peer_mb[tid] + (unsigned)wb * 8);
        }
        // g_h store after the push (off the serial cycle)
        *(float2*)(ghw + (size_t)t * HDIM) = make_float2(h0, h1);
    }
}

// ============================================================================
// Kernel C: out[M,64] = g_h[M,512] @ W_ho[512,64] + b_ho, M = 131072
// ============================================================================
__global__ void __launch_bounds__(256) out_kernel(
    const float* __restrict__ Who, const float* __restrict__ bho,
    float* __restrict__ out)
{
    __shared__ float As[128][17];
    __shared__ float Bs[16][64];
    const int tid = threadIdx.x;
    const int m0 = blockIdx.x * 128;
    const int tx = tid & 15, ty = tid >> 4;

    ull acc[8][2];
#pragma unroll
    for (int i = 0; i < 8; i++) { acc[i][0] = 0ull; acc[i][1] = 0ull; }

    for (int k0 = 0; k0 < HDIM; k0 += 16) {
#pragma unroll
        for (int i = 0; i < 2; i++) {
            int f4  = tid + i * 256;
            int row = f4 >> 2;
            int c4  = (f4 & 3) << 2;
            float4 v = *(const float4*)(g_h + (size_t)(m0 + row) * HDIM + k0 + c4);
            As[row][c4 + 0] = v.x; As[row][c4 + 1] = v.y;
            As[row][c4 + 2] = v.z; As[row][c4 + 3] = v.w;
        }
        {
            int row = tid >> 4;
            int c4  = (tid & 15) << 2;
            *(float4*)&Bs[row][c4] =
                *(const float4*)(Who + (size_t)(k0 + row) * ODIM + c4);
        }
        __syncthreads();
#pragma unroll
        for (int k = 0; k < 16; k++) {
            ulonglong2 bv = *(const ulonglong2*)&Bs[k][tx * 4];
#pragma unroll
            for (int i = 0; i < 8; i++) {
                ull a2 = splat2(As[ty * 8 + i][k]);
                acc[i][0] = ffma2(a2, bv.x, acc[i][0]);
                acc[i][1] = ffma2(a2, bv.y, acc[i][1]);
            }
        }
        __syncthreads();
    }

    float bb0 = bho[tx * 4 + 0], bb1 = bho[tx * 4 + 1];
    float bb2 = bho[tx * 4 + 2], bb3 = bho[tx * 4 + 3];
#pragma unroll
    for (int i = 0; i < 8; i++) {
        float2 v0 = upk2(acc[i][0]); v0.x += bb0; v0.y += bb1;
        float2 v1 = upk2(acc[i][1]); v1.x += bb2; v1.y += bb3;
        float* dst = out + (size_t)(m0 + ty * 8 + i) * ODIM + tx * 4;
        *(float2*)(dst + 0) = v0;
        *(float2*)(dst + 2) = v1;
    }
}

// ============================================================================
extern "C" void kernel_launch(void* const* d_in, const int* in_sizes, int n_in,
                              void* d_out, int out_size)
{
    const float* X   = (const float*)d_in[0];   // [128,1024,256]
    const float* Whh = (const float*)d_in[1];   // [512,512]
    const float* Wih = (const float*)d_in[2];   // [256,512]
    const float* bhh = (const float*)d_in[3];   // [512]
    const float* Who = (const float*)d_in[4];   // [512,64]
    const float* bho = (const float*)d_in[5];   // [64]
    float* out = (float*)d_out;                 // [128,1024,64]

    cudaFuncSetAttribute(rnn_kernel,
                         cudaFuncAttributeMaxDynamicSharedMemorySize,
                         SMEMB_BYTES);

    xproj_kernel<<<dim3(1024, 4, 1), 256>>>(X, Wih, bhh);
    dummy_kernel<<<1, 32>>>();
    dummy_kernel<<<1, 32>>>();
    rnn_kernel<<<128, NT, SMEMB_BYTES>>>(Whh);
    out_kernel<<<1024, 256>>>(Who, bho, out);
}